// round 14
// baseline (speedup 1.0000x reference)
#include <cuda_runtime.h>
#include <cuda_fp16.h>
#include <cstdint>

#define NN 20000
#define NNP 20096   /* padded to 157*128 */
#define NE 320000
#define ET 340000
#define F1 256
#define KK2 512     /* 2*F1: [Ah|Al] x [Bh|Bh], fp16 */
#define HD 512
#define NC 16
#define CNB 148     /* persistent CSR blocks (co-resident) */
#define CSL 136     /* nodes per CSR block: 148*136 >= NN */
#define CEB 2298    /* edges per CSR block: 148*2298 >= ET */

/* ----------------------------- device scratch ---------------------------- */
__device__ __half g_xl1h[(size_t)NN * HD];      /* fp16 xl1 for gather */
__device__ float g_xr1[NN * HD];
__device__ float g_xl2[NN * NC];
__device__ float g_xr2[NN * NC];
__device__ float g_Wt2[HD * 32];                /* [k][32] k-major fused W2 */
__device__ __half g_Ahf[(size_t)NNP * KK2];
__device__ __half g_Bhf[2 * HD * KK2];          /* [z][n][k2] n-major */
__device__ int   g_deg[NN];
__device__ int   g_wp[NN];      /* post-csr: row end (= row start of n+1) */
__device__ int   g_bsum[160];
__device__ int   g_col[ET];
__device__ int   g_cnt, g_gen;  /* grid barrier state (gen monotonic) */

/* --------------------------- helpers ------------------------------------- */
typedef unsigned long long u64;

__device__ __forceinline__ u64 pk2(float x, float y) {
    u64 r;
    asm("mov.b64 %0, {%1, %2};" : "=l"(r)
        : "r"(__float_as_uint(x)), "r"(__float_as_uint(y)));
    return r;
}
__device__ __forceinline__ void fma2(u64& c, u64 a, u64 b) {
    asm("fma.rn.f32x2 %0, %1, %2, %0;" : "+l"(c) : "l"(a), "l"(b));
}
__device__ __forceinline__ u64 add2(u64 a, u64 b) {
    u64 r; asm("add.rn.f32x2 %0, %1, %2;" : "=l"(r) : "l"(a), "l"(b)); return r;
}
__device__ __forceinline__ u64 mul2(u64 a, u64 b) {
    u64 r; asm("mul.rn.f32x2 %0, %1, %2;" : "=l"(r) : "l"(a), "l"(b)); return r;
}
__device__ __forceinline__ float2 upk2(u64 v) {
    unsigned lo, hi;
    asm("mov.b64 {%0, %1}, %2;" : "=r"(lo), "=r"(hi) : "l"(v));
    return make_float2(__uint_as_float(lo), __uint_as_float(hi));
}
__device__ __forceinline__ u64 h2f2(uint32_t h) {
    __half2 hv = *reinterpret_cast<__half2*>(&h);
    float2 f = __half22float2(hv);
    return pk2(f.x, f.y);
}

__device__ __forceinline__ int ev(const void* ei, int is64, int idx) {
    if (is64) return (int)(((const long long*)ei)[idx]);
    return ((const int*)ei)[idx];
}

__device__ __forceinline__ uint32_t smem_u32(const void* p) {
    uint32_t a;
    asm("{ .reg .u64 t; cvta.to.shared.u64 t, %1; cvt.u32.u64 %0, t; }"
        : "=r"(a) : "l"(p));
    return a;
}

__device__ __forceinline__ void cpa16(uint32_t dst, const void* src) {
    asm volatile("cp.async.cg.shared.global [%0], [%1], 16;"
                 :: "r"(dst), "l"(src) : "memory");
}
#define CPA_COMMIT() asm volatile("cp.async.commit_group;" ::: "memory")
#define CPA_WAIT(n)  asm volatile("cp.async.wait_group %0;" :: "n"(n) : "memory")

static __device__ __forceinline__ uint32_t sw128(uint32_t off) {
    return off ^ ((off >> 3) & 0x70);
}

#define LDSM4(r0, r1, r2, r3, a) \
    asm volatile("ldmatrix.sync.aligned.m8n8.x4.shared.b16 {%0,%1,%2,%3}, [%4];" \
                 : "=r"(r0), "=r"(r1), "=r"(r2), "=r"(r3) : "r"(a))

__device__ __forceinline__ void mma16816(float* d, const uint32_t* a,
                                         uint32_t b0, uint32_t b1) {
    asm volatile(
        "mma.sync.aligned.m16n8k16.row.col.f32.f16.f16.f32 "
        "{%0,%1,%2,%3}, {%4,%5,%6,%7}, {%8,%9}, {%0,%1,%2,%3};"
        : "+f"(d[0]), "+f"(d[1]), "+f"(d[2]), "+f"(d[3])
        : "r"(a[0]), "r"(a[1]), "r"(a[2]), "r"(a[3]), "r"(b0), "r"(b1));
}

#define ABS2 0x7FFFFFFF7FFFFFFFull

/* --------------- grid barrier for the persistent CSR kernel --------------- */
__device__ __forceinline__ void gbar() {
    __threadfence();
    __syncthreads();
    if (threadIdx.x == 0) {
        int gen0 = atomicAdd(&g_gen, 0);
        int my = atomicAdd(&g_cnt, 1);
        if (my == CNB - 1) {
            atomicExch(&g_cnt, 0);
            atomicAdd(&g_gen, 1);
        } else {
            while (atomicAdd(&g_gen, 0) == gen0) { }
        }
    }
    __syncthreads();
}

/* ---------------- prep0: A split + B convert + W2 transpose --------------- */
#define W_A (NNP * (F1 / 4))
#define W_B (2 * HD * F1)
#define W_W (HD * NC)
#define NB0 ((W_A + W_B + W_W + 255) / 256)

__global__ void k_prep0(const float* __restrict__ x,
                        const float* __restrict__ W0, const float* __restrict__ W1,
                        const float* __restrict__ Wl2, const float* __restrict__ Wr2)
{
    int idx = blockIdx.x * 256 + threadIdx.x;
    if (idx < W_A) {
        int i = idx;
        int m = i >> 6;
        int c4 = i & 63;
        float4 v = make_float4(0.f, 0.f, 0.f, 0.f);
        if (m < NN) v = reinterpret_cast<const float4*>(x)[i];
        __half hx = __float2half_rn(v.x);
        __half hy = __float2half_rn(v.y);
        __half hz = __float2half_rn(v.z);
        __half hw = __float2half_rn(v.w);
        __half lx = __float2half_rn(v.x - __half2float(hx));
        __half ly = __float2half_rn(v.y - __half2float(hy));
        __half lz = __float2half_rn(v.z - __half2float(hz));
        __half lw = __float2half_rn(v.w - __half2float(hw));
        __half2 h01, h23, l01, l23;
        h01.x = hx; h01.y = hy; h23.x = hz; h23.y = hw;
        l01.x = lx; l01.y = ly; l23.x = lz; l23.y = lw;
        size_t rb = (size_t)m * KK2 + c4 * 4;
        __half2* p0 = reinterpret_cast<__half2*>(&g_Ahf[rb]);
        __half2* p1 = reinterpret_cast<__half2*>(&g_Ahf[rb + F1]);
        p0[0] = h01; p0[1] = h23;
        p1[0] = l01; p1[1] = l23;
    } else if (idx < W_A + W_B) {
        int i = idx - W_A;
        int z = i >> 17;
        int r = i & 131071;
        int n = r >> 8, k = r & 255;
        const float* W = z ? W1 : W0;
        float v = W[(size_t)k * HD + n];
        __half h = __float2half_rn(v);
        size_t base = (size_t)z * HD * KK2 + (size_t)n * KK2;
        g_Bhf[base + k] = h;
        g_Bhf[base + F1 + k] = h;
    } else if (idx < W_A + W_B + W_W) {
        int i = idx - W_A - W_B;
        int k = i >> 4, c = i & 15;
        g_Wt2[k * 32 + c]      = Wl2[i];
        g_Wt2[k * 32 + 16 + c] = Wr2[i];
    }
}

/* --------- k_csr: detect + zero + hist + scan + scatter, one kernel ------- */
__global__ void __launch_bounds__(256) k_csr(const void* __restrict__ ei) {
    __shared__ int s_flag;
    __shared__ int ws[8];
    __shared__ int s_off;

    int b = blockIdx.x, tid = threadIdx.x;
    int lane = tid & 31, wid = tid >> 5;

    /* per-block dtype detect (first 1024 int64 slots' high words) */
    if (tid == 0) s_flag = 0;
    __syncthreads();
    {
        const int* e32 = (const int*)ei;
        int bad = 0;
        #pragma unroll
        for (int i = 0; i < 4; i++) bad |= e32[(tid * 4 + i) * 2 + 1];
        if (bad) atomicOr(&s_flag, 1);
    }
    __syncthreads();
    int is64 = (s_flag == 0) ? 1 : 0;

    /* zero deg slice */
    int nb = b * CSL;
    if (tid < CSL && nb + tid < NN) g_deg[nb + tid] = 0;
    gbar();

    /* hist over edge chunk */
    int eb = b * CEB;
    int ee = eb + CEB; if (ee > ET) ee = ET;
    for (int i = eb + tid; i < ee; i += 256) {
        int dst = (i < NE) ? ev(ei, is64, NE + i) : (i - NE);
        atomicAdd(&g_deg[dst], 1);
    }
    gbar();

    /* block-local exclusive scan of deg slice (L2 reads: __ldcg) */
    int v = 0;
    if (tid < CSL && nb + tid < NN) v = __ldcg(&g_deg[nb + tid]);
    int x = v;
    #pragma unroll
    for (int off = 1; off < 32; off <<= 1) {
        int t = __shfl_up_sync(0xffffffffu, x, off);
        if (lane >= off) x += t;
    }
    if (lane == 31) ws[wid] = x;
    __syncthreads();
    if (wid == 0 && lane < 8) {
        int y = ws[lane];
        #pragma unroll
        for (int o = 1; o < 8; o <<= 1) {
            int t = __shfl_up_sync(0x000000ffu, y, o, 8);
            if (lane >= o) y += t;
        }
        ws[lane] = y;
    }
    __syncthreads();
    int excl = (wid ? ws[wid - 1] : 0) + x - v;
    if (tid < CSL && nb + tid < NN) g_wp[nb + tid] = excl;
    if (tid == 0) g_bsum[b] = ws[7];
    gbar();

    /* block offset = sum of previous block totals; add to slice */
    if (tid < 32) {
        int accp = 0;
        for (int k = tid; k < b; k += 32) accp += __ldcg(&g_bsum[k]);
        #pragma unroll
        for (int o = 16; o; o >>= 1) accp += __shfl_xor_sync(0xffffffffu, accp, o);
        if (tid == 0) s_off = accp;
    }
    __syncthreads();
    if (tid < CSL && nb + tid < NN) g_wp[nb + tid] += s_off;
    gbar();

    /* scatter */
    for (int i = eb + tid; i < ee; i += 256) {
        int src, dst;
        if (i < NE) { src = ev(ei, is64, i); dst = ev(ei, is64, NE + i); }
        else        { src = i - NE; dst = i - NE; }
        int pos = atomicAdd(&g_wp[dst], 1);
        g_col[pos] = src;
    }
}
/* after k_csr: g_wp[n] == row_end(n) == row_start(n+1) */

/* -------------------- 2xFP16 HMMA GEMM, 3-stage, 2 CTA/SM ----------------- */
#define BK 64
#define NIT (KK2 / BK)        /* 8 */
#define STG 16384

__global__ void __launch_bounds__(256, 2)
k_hmma(const float* __restrict__ b0, const float* __restrict__ b1)
{
    extern __shared__ char dyn[];
    uint32_t SB = (smem_u32(dyn) + 1023u) & ~1023u;

    int tid = threadIdx.x;
    int lane = tid & 31, wid = tid >> 5;
    int warp_m = wid >> 2, warp_n = wid & 3;
    int bm = blockIdx.x * 128;
    int bn = blockIdx.y * 128;
    int z  = blockIdx.z;

    const __half* Asrc = g_Ahf + (size_t)bm * KK2;
    const __half* Bsrc = g_Bhf + (size_t)z * HD * KK2 + (size_t)bn * KK2;

    int lr = tid >> 1;
    int lc = (tid & 1) << 2;
    auto load_tiles = [&](int it, int s) {
        int k0 = it * BK;
        uint32_t Ab = SB + (uint32_t)s * (2 * STG);
        uint32_t Bb = Ab + STG;
        #pragma unroll
        for (int i = 0; i < 4; i++) {
            int cj = lc + i;
            cpa16(Ab + sw128((uint32_t)(lr * 128 + cj * 16)),
                  Asrc + (size_t)lr * KK2 + k0 + cj * 8);
            cpa16(Bb + sw128((uint32_t)(lr * 128 + cj * 16)),
                  Bsrc + (size_t)lr * KK2 + k0 + cj * 8);
        }
        CPA_COMMIT();
    };

    float d[4][4][4];
    #pragma unroll
    for (int i = 0; i < 4; i++)
        #pragma unroll
        for (int j = 0; j < 4; j++)
            #pragma unroll
            for (int q = 0; q < 4; q++) d[i][j][q] = 0.f;

    load_tiles(0, 0);
    load_tiles(1, 1);

    int l15 = lane & 15;
    int kb_lane = (lane & 16);

    #pragma unroll 1
    for (int it = 0; it < NIT; it++) {
        if (it + 1 < NIT) { CPA_WAIT(1); } else { CPA_WAIT(0); }
        __syncthreads();
        if (it + 2 < NIT) load_tiles(it + 2, (it + 2) % 3);

        uint32_t Ab = SB + (uint32_t)(it % 3) * (2 * STG);
        uint32_t Bb = Ab + STG;

        #pragma unroll
        for (int ks = 0; ks < 4; ks++) {
            uint32_t a[4][4];
            #pragma unroll
            for (int mi = 0; mi < 4; mi++) {
                uint32_t off = (uint32_t)((warp_m * 64 + mi * 16 + l15) * 128
                                          + ks * 32 + kb_lane);
                LDSM4(a[mi][0], a[mi][1], a[mi][2], a[mi][3], Ab + sw128(off));
            }
            uint32_t bf[2][4];
            #pragma unroll
            for (int bj = 0; bj < 2; bj++) {
                uint32_t off = (uint32_t)((warp_n * 32 + bj * 16 + l15) * 128
                                          + ks * 32 + kb_lane);
                LDSM4(bf[bj][0], bf[bj][1], bf[bj][2], bf[bj][3], Bb + sw128(off));
            }
            #pragma unroll
            for (int mi = 0; mi < 4; mi++)
                #pragma unroll
                for (int nj = 0; nj < 4; nj++) {
                    int bj = nj >> 1, sel = nj & 1;
                    mma16816(d[mi][nj], a[mi], bf[bj][sel], bf[bj][sel + 2]);
                }
        }
        __syncthreads();
    }

    const float* bias = z ? b1 : b0;
    int colb = bn + warp_n * 32 + (lane & 3) * 2;
    int rowb = bm + warp_m * 64 + (lane >> 2);
    #pragma unroll
    for (int nj = 0; nj < 4; nj++) {
        int col = colb + nj * 8;
        float2 bv = *reinterpret_cast<const float2*>(bias + col);
        #pragma unroll
        for (int mi = 0; mi < 4; mi++) {
            int r0 = rowb + mi * 16;
            if (z == 0) {
                if (r0 < NN) {
                    __half2 ho = __floats2half2_rn(d[mi][nj][0] + bv.x,
                                                   d[mi][nj][1] + bv.y);
                    *reinterpret_cast<__half2*>(g_xl1h + (size_t)r0 * HD + col) = ho;
                }
                if (r0 + 8 < NN) {
                    __half2 ho = __floats2half2_rn(d[mi][nj][2] + bv.x,
                                                   d[mi][nj][3] + bv.y);
                    *reinterpret_cast<__half2*>(g_xl1h + (size_t)(r0 + 8) * HD + col) = ho;
                }
            } else {
                if (r0 < NN) {
                    float2 o = make_float2(d[mi][nj][0] + bv.x, d[mi][nj][1] + bv.y);
                    *reinterpret_cast<float2*>(g_xr1 + (size_t)r0 * HD + col) = o;
                }
                if (r0 + 8 < NN) {
                    float2 o = make_float2(d[mi][nj][2] + bv.x, d[mi][nj][3] + bv.y);
                    *reinterpret_cast<float2*>(g_xr1 + (size_t)(r0 + 8) * HD + col) = o;
                }
            }
        }
    }
}

/* ------ layer-1 GATv2 fused with layer-2 linear, pipelined gathers -------- */
__global__ void __launch_bounds__(256)
k_gat1(const float* __restrict__ xr,
       const float* __restrict__ att, const float* __restrict__ bias,
       const float* __restrict__ bl, const float* __restrict__ br_,
       float* __restrict__ xl2, float* __restrict__ xr2)
{
    __shared__ __align__(16) float hsm[4][HD];
    __shared__ float2 part[4][16];

    int tid = threadIdx.x;
    int nl = tid >> 6;
    int node = blockIdx.x * 4 + nl;
    int u = tid & 63;

    const ulonglong2* xrp = reinterpret_cast<const ulonglong2*>(xr);
    const ulonglong2* atp = reinterpret_cast<const ulonglong2*>(att);
    const uint4* xlp = reinterpret_cast<const uint4*>(g_xl1h);

    ulonglong2 x01 = xrp[(size_t)node * 128 + u * 2];
    ulonglong2 x23 = xrp[(size_t)node * 128 + u * 2 + 1];
    u64 xp[4] = {x01.x, x01.y, x23.x, x23.y};

    ulonglong2 a01 = atp[u * 2];
    ulonglong2 a23 = atp[u * 2 + 1];
    u64 araw[4] = {a01.x, a01.y, a23.x, a23.y};
    u64 a6[4], a4[4];
    const u64 c6 = pk2(0.6f, 0.6f), c4 = pk2(0.4f, 0.4f);
    #pragma unroll
    for (int j = 0; j < 4; j++) { a6[j] = mul2(araw[j], c6); a4[j] = mul2(araw[j], c4); }

    float4 bv0 = reinterpret_cast<const float4*>(bias)[u * 2];
    float4 bv1 = reinterpret_cast<const float4*>(bias)[u * 2 + 1];

    int jb = node ? g_wp[node - 1] : 0;
    int je = g_wp[node];
    int rem = je - jb;

    float m = -1e30f, s = 0.f;
    u64 acc[4] = {0ull, 0ull, 0ull, 0ull};

    uint4 v0, v1;
    if (rem >= 2) {
        int p0 = g_col[jb], p1 = g_col[jb + 1];
        v0 = xlp[(size_t)p0 * 64 + u];
        v1 = xlp[(size_t)p1 * 64 + u];
    }
    int j = jb;
    for (; j + 2 <= je; j += 2) {
        uint4 cur0 = v0, cur1 = v1;
        int left = je - (j + 2);
        if (left >= 2) {
            int p0 = g_col[j + 2], p1 = g_col[j + 3];
            v0 = xlp[(size_t)p0 * 64 + u];
            v1 = xlp[(size_t)p1 * 64 + u];
        } else if (left == 1) {
            int p0 = g_col[j + 2];
            v0 = xlp[(size_t)p0 * 64 + u];
        }

        u64 c0[4] = {h2f2(cur0.x), h2f2(cur0.y), h2f2(cur0.z), h2f2(cur0.w)};
        u64 c1[4] = {h2f2(cur1.x), h2f2(cur1.y), h2f2(cur1.z), h2f2(cur1.w)};

        u64 e20 = 0ull, e21 = 0ull;
        #pragma unroll
        for (int q = 0; q < 4; q++) {
            u64 t0 = add2(c0[q], xp[q]);
            u64 t1 = add2(c1[q], xp[q]);
            fma2(e20, a6[q], t0);
            fma2(e21, a6[q], t1);
            fma2(e20, a4[q], t0 & ABS2);
            fma2(e21, a4[q], t1 & ABS2);
        }
        float2 f0 = upk2(e20), f1 = upk2(e21);
        float e0 = f0.x + f0.y, e1 = f1.x + f1.y;
        e0 += __shfl_xor_sync(0xffffffffu, e0, 1, 8);
        e1 += __shfl_xor_sync(0xffffffffu, e1, 1, 8);
        e0 += __shfl_xor_sync(0xffffffffu, e0, 2, 8);
        e1 += __shfl_xor_sync(0xffffffffu, e1, 2, 8);
        e0 += __shfl_xor_sync(0xffffffffu, e0, 4, 8);
        e1 += __shfl_xor_sync(0xffffffffu, e1, 4, 8);

        float nm = fmaxf(m, fmaxf(e0, e1));
        float sc = __expf(m - nm);
        float w0 = __expf(e0 - nm);
        float w1 = __expf(e1 - nm);
        s = s * sc + w0 + w1;
        u64 scp = pk2(sc, sc), w0p = pk2(w0, w0), w1p = pk2(w1, w1);
        #pragma unroll
        for (int q = 0; q < 4; q++) {
            acc[q] = mul2(acc[q], scp);
            fma2(acc[q], w0p, c0[q]);
            fma2(acc[q], w1p, c1[q]);
        }
        m = nm;
    }
    if (rem & 1) {
        uint4 cur;
        if (rem == 1) { int p0 = g_col[jb]; cur = xlp[(size_t)p0 * 64 + u]; }
        else cur = v0;
        u64 c0[4] = {h2f2(cur.x), h2f2(cur.y), h2f2(cur.z), h2f2(cur.w)};
        u64 e20 = 0ull;
        #pragma unroll
        for (int q = 0; q < 4; q++) {
            u64 t0 = add2(c0[q], xp[q]);
            fma2(e20, a6[q], t0);
            fma2(e20, a4[q], t0 & ABS2);
        }
        float2 f0 = upk2(e20);
        float e0 = f0.x + f0.y;
        e0 += __shfl_xor_sync(0xffffffffu, e0, 1, 8);
        e0 += __shfl_xor_sync(0xffffffffu, e0, 2, 8);
        e0 += __shfl_xor_sync(0xffffffffu, e0, 4, 8);
        float nm = fmaxf(m, e0);
        float sc = __expf(m - nm);
        float w0 = __expf(e0 - nm);
        s = s * sc + w0;
        u64 scp = pk2(sc, sc), w0p = pk2(w0, w0);
        #pragma unroll
        for (int q = 0; q < 4; q++) {
            acc[q] = mul2(acc[q], scp);
            fma2(acc[q], w0p, c0[q]);
        }
        m = nm;
    }

    float inv = 1.f / s;
    float2 r0 = upk2(acc[0]), r1 = upk2(acc[1]);
    float2 r2 = upk2(acc[2]), r3 = upk2(acc[3]);
    float4 o0, o1;
    o0.x = fmaxf(r0.x * inv + bv0.x, 0.f);
    o0.y = fmaxf(r0.y * inv + bv0.y, 0.f);
    o0.z = fmaxf(r1.x * inv + bv0.z, 0.f);
    o0.w = fmaxf(r1.y * inv + bv0.w, 0.f);
    o1.x = fmaxf(r2.x * inv + bv1.x, 0.f);
    o1.y = fmaxf(r2.y * inv + bv1.y, 0.f);
    o1.z = fmaxf(r3.x * inv + bv1.z, 0.f);
    o1.w = fmaxf(r3.y * inv + bv1.w, 0.f);

    float4* hs4 = reinterpret_cast<float4*>(hsm[nl]);
    hs4[u * 2] = o0;
    hs4[u * 2 + 1] = o1;
    __syncthreads();

    /* fused layer-2 linear: warp pair per node, split-k quarters */
    int wid = tid >> 5, lane = tid & 31;
    int n2 = wid >> 1;
    int qk = ((wid & 1) << 1) | (lane >> 4);
    int c = lane & 15;

    const u64* wp = reinterpret_cast<const u64*>(g_Wt2) + c;
    const float* hrow = hsm[n2];
    u64 acc2 = 0ull;
    int k0 = qk * 128;
    #pragma unroll 8
    for (int k = k0; k < k0 + 128; k++) {
        float hv = hrow[k];
        fma2(acc2, pk2(hv, hv), wp[(size_t)k * 16]);
    }
    float2 f = upk2(acc2);
    f.x += __shfl_xor_sync(0xffffffffu, f.x, 16);
    f.y += __shfl_xor_sync(0xffffffffu, f.y, 16);
    if ((wid & 1) == 1 && lane < 16) part[n2][c] = f;
    __syncthreads();
    if ((wid & 1) == 0 && lane < 16) {
        float2 p2 = part[n2][c];
        float rx = f.x + p2.x, ry = f.y + p2.y;
        int g = blockIdx.x * 4 + n2;
        int col = 2 * c;
        if (col < 16) {
            xl2[(size_t)g * NC + col]     = rx + bl[col];
            xl2[(size_t)g * NC + col + 1] = ry + bl[col + 1];
        } else {
            int cc = col - 16;
            xr2[(size_t)g * NC + cc]     = rx + br_[cc];
            xr2[(size_t)g * NC + cc + 1] = ry + br_[cc + 1];
        }
    }
}

/* --------------------- layer-2 GATv2: 4 lanes/node ------------------------ */
__global__ void __launch_bounds__(256)
k_gat2(const float* __restrict__ xl, const float* __restrict__ xr,
       const float* __restrict__ att, const float* __restrict__ bias,
       float* __restrict__ out)
{
    int tid = threadIdx.x;
    int node = blockIdx.x * 64 + (tid >> 2);
    int q = tid & 3;
    if (node >= NN) return;

    const float4* xlp = reinterpret_cast<const float4*>(xl);
    float4 xrv = reinterpret_cast<const float4*>(xr)[(size_t)node * 4 + q];
    float4 avr = reinterpret_cast<const float4*>(att)[q];
    float4 a6 = make_float4(avr.x * 0.6f, avr.y * 0.6f, avr.z * 0.6f, avr.w * 0.6f);
    float4 a4 = make_float4(avr.x * 0.4f, avr.y * 0.4f, avr.z * 0.4f, avr.w * 0.4f);

    int jb = node ? g_wp[node - 1] : 0;
    int je = g_wp[node];

    float m = -1e30f, s = 0.f;
    float4 acc = make_float4(0.f, 0.f, 0.f, 0.f);

    int j = jb;
    for (; j + 2 <= je; j += 2) {
        int s0 = g_col[j], s1 = g_col[j + 1];
        float4 c0 = xlp[(size_t)s0 * 4 + q];
        float4 c1 = xlp[(size_t)s1 * 4 + q];
        float4 t0, t1;
        t0.x = c0.x + xrv.x; t0.y = c0.y + xrv.y; t0.z = c0.z + xrv.z; t0.w = c0.w + xrv.w;
        t1.x = c1.x + xrv.x; t1.y = c1.y + xrv.y; t1.z = c1.z + xrv.z; t1.w = c1.w + xrv.w;
        float e0 = fmaf(a4.x, fabsf(t0.x), a6.x * t0.x);
        e0 = fmaf(a6.y, t0.y, fmaf(a4.y, fabsf(t0.y), e0));
        e0 = fmaf(a6.z, t0.z, fmaf(a4.z, fabsf(t0.z), e0));
        e0 = fmaf(a6.w, t0.w, fmaf(a4.w, fabsf(t0.w), e0));
        float e1 = fmaf(a4.x, fabsf(t1.x), a6.x * t1.x);
        e1 = fmaf(a6.y, t1.y, fmaf(a4.y, fabsf(t1.y), e1));
        e1 = fmaf(a6.z, t1.z, fmaf(a4.z, fabsf(t1.z), e1));
        e1 = fmaf(a6.w, t1.w, fmaf(a4.w, fabsf(t1.w), e1));
        e0 += __shfl_xor_sync(0xffffffffu, e0, 1, 4);
        e1 += __shfl_xor_sync(0xffffffffu, e1, 1, 4);
        e0 += __shfl_xor_sync(0xffffffffu, e0, 2, 4);
        e1 += __shfl_xor_sync(0xffffffffu, e1, 2, 4);

        float nm = fmaxf(m, fmaxf(e0, e1));
        float sc = __expf(m - nm);
        float w0 = __expf(e0 - nm);
        float w1 = __expf(e1 - nm);
        s = s * sc + w0 + w1;
        acc.x = fmaf(w1, c1.x, fmaf(w0, c0.x, acc.x * sc));
        acc.y = fmaf(w1, c1.y, fmaf(w0, c0.y, acc.y * sc));
        acc.z = fmaf(w1, c1.z, fmaf(w0, c0.z, acc.z * sc));
        acc.w = fmaf(w1, c1.w, fmaf(w0, c0.w, acc.w * sc));
        m = nm;
    }
    for (; j < je; j++) {
        int s0 = g_col[j];
        float4 c0 = xlp[(size_t)s0 * 4 + q];
        float4 t0;
        t0.x = c0.x + xrv.x; t0.y = c0.y + xrv.y; t0.z = c0.z + xrv.z; t0.w = c0.w + xrv.w;
        float e0 = fmaf(a4.x, fabsf(t0.x), a6.x * t0.x);
        e0 = fmaf(a6.y, t0.y, fmaf(a4.y, fabsf(t0.y), e0));
        e0 = fmaf(a6.z, t0.z, fmaf(a4.z, fabsf(t0.z), e0));
        e0 = fmaf(a6.w, t0.w, fmaf(a4.w, fabsf(t0.w), e0));
        e0 += __shfl_xor_sync(0xffffffffu, e0, 1, 4);
        e0 += __shfl_xor_sync(0xffffffffu, e0, 2, 4);
        float nm = fmaxf(m, e0);
        float sc = __expf(m - nm);
        float w0 = __expf(e0 - nm);
        s = s * sc + w0;
        acc.x = fmaf(w0, c0.x, acc.x * sc);
        acc.y = fmaf(w0, c0.y, acc.y * sc);
        acc.z = fmaf(w0, c0.z, acc.z * sc);
        acc.w = fmaf(w0, c0.w, acc.w * sc);
        m = nm;
    }

    float inv = 1.f / s;
    float4 bvq = reinterpret_cast<const float4*>(bias)[q];
    float4 o;
    o.x = acc.x * inv + bvq.x;
    o.y = acc.y * inv + bvq.y;
    o.z = acc.z * inv + bvq.z;
    o.w = acc.w * inv + bvq.w;
    reinterpret_cast<float4*>(out)[(size_t)node * 4 + q] = o;
}

/* ------------------------------- launch ---------------------------------- */
extern "C" void kernel_launch(void* const* d_in, const int* in_sizes, int n_in,
                              void* d_out, int out_size)
{
    const float* x     = (const float*)d_in[0];
    const void*  ei    = d_in[1];
    const float* W_l1  = (const float*)d_in[2];
    const float* b_l1  = (const float*)d_in[3];
    const float* W_r1  = (const float*)d_in[4];
    const float* b_r1  = (const float*)d_in[5];
    const float* att1  = (const float*)d_in[6];
    const float* bias1 = (const float*)d_in[7];
    const float* W_l2  = (const float*)d_in[8];
    const float* b_l2  = (const float*)d_in[9];
    const float* W_r2  = (const float*)d_in[10];
    const float* b_r2  = (const float*)d_in[11];
    const float* att2  = (const float*)d_in[12];
    const float* bias2 = (const float*)d_in[13];
    float* out = (float*)d_out;

    static cudaStream_t s2 = 0;
    static cudaEvent_t evF = 0, evB = 0;
    if (s2 == 0) {
        cudaStreamCreateWithFlags(&s2, cudaStreamNonBlocking);
        cudaEventCreateWithFlags(&evF, cudaEventDisableTiming);
        cudaEventCreateWithFlags(&evB, cudaEventDisableTiming);
    }

    float *xr1, *xl2, *xr2;
    cudaGetSymbolAddress((void**)&xr1, g_xr1);
    cudaGetSymbolAddress((void**)&xl2, g_xl2);
    cudaGetSymbolAddress((void**)&xr2, g_xr2);

    cudaFuncSetAttribute(k_hmma, cudaFuncAttributeMaxDynamicSharedMemorySize, 6 * STG + 1024);

    /* fork FIRST (from the captured stream), so the CSR branch joins the
       capture graph without serializing behind prep0 */
    cudaEventRecord(evF, 0);
    cudaStreamWaitEvent(s2, evF, 0);
    k_csr<<<CNB, 256, 0, s2>>>(ei);                            /* side branch */
    cudaEventRecord(evB, s2);

    k_prep0<<<NB0, 256>>>(x, W_l1, W_r1, W_l2, W_r2);          /* s0 */

    dim3 gm(NNP / 128, HD / 128, 2);
    k_hmma<<<gm, 256, 6 * STG + 1024>>>(b_l1, b_r1);           /* s0 */

    cudaStreamWaitEvent(0, evB, 0);
    k_gat1<<<NN / 4, 256>>>(xr1, att1, bias1, b_l2, b_r2, xl2, xr2);  /* 4th kernel → profiled */
    k_gat2<<<(NN + 63) / 64, 256>>>(xl2, xr2, att2, bias2, out);
}

// round 15
// speedup vs baseline: 1.1619x; 1.1619x over previous
#include <cuda_runtime.h>
#include <cuda_fp16.h>
#include <cstdint>

#define NN 20000
#define NNP 20096
#define NE 320000
#define ET 340000
#define F1 256
#define KK2 512
#define HD 512
#define NC 16
#define NBS 79

/* ----------------------------- device scratch ---------------------------- */
__device__ __half g_xl1h[(size_t)NN * HD];
__device__ float g_xr1[NN * HD];
__device__ float g_xl2[NN * NC];
__device__ float g_xr2[NN * NC];
__device__ float g_Wt2[HD * 32];
__device__ __half g_Ahf[(size_t)NNP * KK2];
__device__ __half g_Bhf[2 * HD * KK2];
__device__ int   g_deg[NN];
__device__ int   g_wp[NN];
__device__ int   g_bsum[96];
__device__ int   g_col[ET];
__device__ int   g_is64;

/* --------------------------- helpers ------------------------------------- */
typedef unsigned long long u64;

__device__ __forceinline__ u64 pk2(float x, float y) {
    u64 r;
    asm("mov.b64 %0, {%1, %2};" : "=l"(r)
        : "r"(__float_as_uint(x)), "r"(__float_as_uint(y)));
    return r;
}
__device__ __forceinline__ void fma2(u64& c, u64 a, u64 b) {
    asm("fma.rn.f32x2 %0, %1, %2, %0;" : "+l"(c) : "l"(a), "l"(b));
}
__device__ __forceinline__ u64 add2(u64 a, u64 b) {
    u64 r; asm("add.rn.f32x2 %0, %1, %2;" : "=l"(r) : "l"(a), "l"(b)); return r;
}
__device__ __forceinline__ u64 mul2(u64 a, u64 b) {
    u64 r; asm("mul.rn.f32x2 %0, %1, %2;" : "=l"(r) : "l"(a), "l"(b)); return r;
}
__device__ __forceinline__ float2 upk2(u64 v) {
    unsigned lo, hi;
    asm("mov.b64 {%0, %1}, %2;" : "=r"(lo), "=r"(hi) : "l"(v));
    return make_float2(__uint_as_float(lo), __uint_as_float(hi));
}
__device__ __forceinline__ u64 h2f2(uint32_t h) {
    __half2 hv = *reinterpret_cast<__half2*>(&h);
    float2 f = __half22float2(hv);
    return pk2(f.x, f.y);
}

__device__ __forceinline__ int edge_val(const void* ei, int idx) {
    if (g_is64) return (int)(((const long long*)ei)[idx]);
    return ((const int*)ei)[idx];
}

__device__ __forceinline__ uint32_t smem_u32(const void* p) {
    uint32_t a;
    asm("{ .reg .u64 t; cvta.to.shared.u64 t, %1; cvt.u32.u64 %0, t; }"
        : "=r"(a) : "l"(p));
    return a;
}

__device__ __forceinline__ void cpa16(uint32_t dst, const void* src) {
    asm volatile("cp.async.cg.shared.global [%0], [%1], 16;"
                 :: "r"(dst), "l"(src) : "memory");
}
#define CPA_COMMIT() asm volatile("cp.async.commit_group;" ::: "memory")
#define CPA_WAIT(n)  asm volatile("cp.async.wait_group %0;" :: "n"(n) : "memory")

static __device__ __forceinline__ uint32_t sw128(uint32_t off) {
    return off ^ ((off >> 3) & 0x70);
}

#define LDSM4(r0, r1, r2, r3, a) \
    asm volatile("ldmatrix.sync.aligned.m8n8.x4.shared.b16 {%0,%1,%2,%3}, [%4];" \
                 : "=r"(r0), "=r"(r1), "=r"(r2), "=r"(r3) : "r"(a))

__device__ __forceinline__ void mma16816(float* d, const uint32_t* a,
                                         uint32_t b0, uint32_t b1) {
    asm volatile(
        "mma.sync.aligned.m16n8k16.row.col.f32.f16.f16.f32 "
        "{%0,%1,%2,%3}, {%4,%5,%6,%7}, {%8,%9}, {%0,%1,%2,%3};"
        : "+f"(d[0]), "+f"(d[1]), "+f"(d[2]), "+f"(d[3])
        : "r"(a[0]), "r"(a[1]), "r"(a[2]), "r"(a[3]), "r"(b0), "r"(b1));
}

#define ABS2 0x7FFFFFFF7FFFFFFFull

/* ------ prep0: A split + B convert + W2 transpose + deg zero + detect ----- */
#define W_A (NNP * (F1 / 4))
#define W_B (2 * HD * F1)
#define W_W (HD * NC)
#define NB0 ((W_A + W_B + W_W + 255) / 256)

__global__ void k_prep0(const float* __restrict__ x,
                        const float* __restrict__ W0, const float* __restrict__ W1,
                        const float* __restrict__ Wl2, const float* __restrict__ Wr2,
                        const int* __restrict__ ei32)
{
    if (blockIdx.x >= NB0) {
        int b = blockIdx.x - NB0;
        if (b < NBS) {
            int i = b * 256 + threadIdx.x;
            if (i < NN) g_deg[i] = 0;
        } else {
            __shared__ int sflag;
            int tid = threadIdx.x;
            if (tid == 0) sflag = 0;
            __syncthreads();
            int bad = 0;
            #pragma unroll
            for (int i = 0; i < 4; i++) bad |= ei32[(tid * 4 + i) * 2 + 1];
            if (bad) atomicOr(&sflag, 1);
            __syncthreads();
            if (tid == 0) g_is64 = (sflag == 0) ? 1 : 0;
        }
        return;
    }

    int idx = blockIdx.x * 256 + threadIdx.x;
    if (idx < W_A) {
        int i = idx;
        int m = i >> 6;
        int c4 = i & 63;
        float4 v = make_float4(0.f, 0.f, 0.f, 0.f);
        if (m < NN) v = reinterpret_cast<const float4*>(x)[i];
        __half hx = __float2half_rn(v.x);
        __half hy = __float2half_rn(v.y);
        __half hz = __float2half_rn(v.z);
        __half hw = __float2half_rn(v.w);
        __half lx = __float2half_rn(v.x - __half2float(hx));
        __half ly = __float2half_rn(v.y - __half2float(hy));
        __half lz = __float2half_rn(v.z - __half2float(hz));
        __half lw = __float2half_rn(v.w - __half2float(hw));
        __half2 h01, h23, l01, l23;
        h01.x = hx; h01.y = hy; h23.x = hz; h23.y = hw;
        l01.x = lx; l01.y = ly; l23.x = lz; l23.y = lw;
        size_t rb = (size_t)m * KK2 + c4 * 4;
        __half2* p0 = reinterpret_cast<__half2*>(&g_Ahf[rb]);
        __half2* p1 = reinterpret_cast<__half2*>(&g_Ahf[rb + F1]);
        p0[0] = h01; p0[1] = h23;
        p1[0] = l01; p1[1] = l23;
    } else if (idx < W_A + W_B) {
        int i = idx - W_A;
        int z = i >> 17;
        int r = i & 131071;
        int n = r >> 8, k = r & 255;
        const float* W = z ? W1 : W0;
        float v = W[(size_t)k * HD + n];
        __half h = __float2half_rn(v);
        size_t base = (size_t)z * HD * KK2 + (size_t)n * KK2;
        g_Bhf[base + k] = h;
        g_Bhf[base + F1 + k] = h;
    } else if (idx < W_A + W_B + W_W) {
        int i = idx - W_A - W_B;
        int k = i >> 4, c = i & 15;
        g_Wt2[k * 32 + c]      = Wl2[i];
        g_Wt2[k * 32 + 16 + c] = Wr2[i];
    }
}

/* ------------------------------- CSR build ------------------------------- */
__global__ void k_hist(const void* __restrict__ ei) {
    int i = blockIdx.x * blockDim.x + threadIdx.x;
    if (i >= ET) return;
    int dst = (i < NE) ? edge_val(ei, NE + i) : (i - NE);
    atomicAdd(&g_deg[dst], 1);
}

__global__ void __launch_bounds__(256) k_scanA() {
    __shared__ int wsum[8];
    int b = blockIdx.x, tid = threadIdx.x, lane = tid & 31, wid = tid >> 5;
    int i = b * 256 + tid;
    int v = (i < NN) ? g_deg[i] : 0;
    int x = v;
    #pragma unroll
    for (int off = 1; off < 32; off <<= 1) {
        int t = __shfl_up_sync(0xffffffffu, x, off);
        if (lane >= off) x += t;
    }
    if (lane == 31) wsum[wid] = x;
    __syncthreads();
    if (wid == 0 && lane < 8) {
        int y = wsum[lane];
        #pragma unroll
        for (int off = 1; off < 8; off <<= 1) {
            int t = __shfl_up_sync(0x000000ffu, y, off, 8);
            if (lane >= off) y += t;
        }
        wsum[lane] = y;
    }
    __syncthreads();
    int base = wid ? wsum[wid - 1] : 0;
    int incl = base + x;
    if (i < NN) g_wp[i] = incl - v;
    if (tid == 255) g_bsum[b] = wsum[7];
}

__global__ void __launch_bounds__(1024) k_scanB() {
    __shared__ int off[NBS + 1];
    int tid = threadIdx.x, lane = tid & 31, wid = tid >> 5;
    if (wid == 0) {
        int carry = 0;
        #pragma unroll
        for (int c = 0; c < 3; c++) {
            int idx = c * 32 + lane;
            int v = (idx < NBS) ? g_bsum[idx] : 0;
            int x = v;
            #pragma unroll
            for (int o = 1; o < 32; o <<= 1) {
                int t = __shfl_up_sync(0xffffffffu, x, o);
                if (lane >= o) x += t;
            }
            if (idx < NBS) off[idx] = carry + x - v;
            carry += __shfl_sync(0xffffffffu, x, 31);
        }
    }
    __syncthreads();
    for (int i = tid; i < NN; i += 1024) g_wp[i] += off[i >> 8];
}

__global__ void k_scatter(const void* __restrict__ ei) {
    int i = blockIdx.x * blockDim.x + threadIdx.x;
    if (i >= ET) return;
    int src, dst;
    if (i < NE) { src = edge_val(ei, i); dst = edge_val(ei, NE + i); }
    else        { src = i - NE; dst = i - NE; }
    int pos = atomicAdd(&g_wp[dst], 1);
    g_col[pos] = src;
}
/* after k_scatter: g_wp[n] == row_end(n) == row_start(n+1) */

/* -------------------- 2xFP16 HMMA GEMM, 3-stage, 2 CTA/SM ----------------- */
#define BK 64
#define NIT (KK2 / BK)
#define STG 16384

__global__ void __launch_bounds__(256, 2)
k_hmma(const float* __restrict__ b0, const float* __restrict__ b1)
{
    extern __shared__ char dyn[];
    uint32_t SB = (smem_u32(dyn) + 1023u) & ~1023u;

    int tid = threadIdx.x;
    int lane = tid & 31, wid = tid >> 5;
    int warp_m = wid >> 2, warp_n = wid & 3;
    int bm = blockIdx.x * 128;
    int bn = blockIdx.y * 128;
    int z  = blockIdx.z;

    const __half* Asrc = g_Ahf + (size_t)bm * KK2;
    const __half* Bsrc = g_Bhf + (size_t)z * HD * KK2 + (size_t)bn * KK2;

    int lr = tid >> 1;
    int lc = (tid & 1) << 2;
    auto load_tiles = [&](int it, int s) {
        int k0 = it * BK;
        uint32_t Ab = SB + (uint32_t)s * (2 * STG);
        uint32_t Bb = Ab + STG;
        #pragma unroll
        for (int i = 0; i < 4; i++) {
            int cj = lc + i;
            cpa16(Ab + sw128((uint32_t)(lr * 128 + cj * 16)),
                  Asrc + (size_t)lr * KK2 + k0 + cj * 8);
            cpa16(Bb + sw128((uint32_t)(lr * 128 + cj * 16)),
                  Bsrc + (size_t)lr * KK2 + k0 + cj * 8);
        }
        CPA_COMMIT();
    };

    float d[4][4][4];
    #pragma unroll
    for (int i = 0; i < 4; i++)
        #pragma unroll
        for (int j = 0; j < 4; j++)
            #pragma unroll
            for (int q = 0; q < 4; q++) d[i][j][q] = 0.f;

    load_tiles(0, 0);
    load_tiles(1, 1);

    int l15 = lane & 15;
    int kb_lane = (lane & 16);

    #pragma unroll 1
    for (int it = 0; it < NIT; it++) {
        if (it + 1 < NIT) { CPA_WAIT(1); } else { CPA_WAIT(0); }
        __syncthreads();
        if (it + 2 < NIT) load_tiles(it + 2, (it + 2) % 3);

        uint32_t Ab = SB + (uint32_t)(it % 3) * (2 * STG);
        uint32_t Bb = Ab + STG;

        #pragma unroll
        for (int ks = 0; ks < 4; ks++) {
            uint32_t a[4][4];
            #pragma unroll
            for (int mi = 0; mi < 4; mi++) {
                uint32_t off = (uint32_t)((warp_m * 64 + mi * 16 + l15) * 128
                                          + ks * 32 + kb_lane);
                LDSM4(a[mi][0], a[mi][1], a[mi][2], a[mi][3], Ab + sw128(off));
            }
            uint32_t bf[2][4];
            #pragma unroll
            for (int bj = 0; bj < 2; bj++) {
                uint32_t off = (uint32_t)((warp_n * 32 + bj * 16 + l15) * 128
                                          + ks * 32 + kb_lane);
                LDSM4(bf[bj][0], bf[bj][1], bf[bj][2], bf[bj][3], Bb + sw128(off));
            }
            #pragma unroll
            for (int mi = 0; mi < 4; mi++)
                #pragma unroll
                for (int nj = 0; nj < 4; nj++) {
                    int bj = nj >> 1, sel = nj & 1;
                    mma16816(d[mi][nj], a[mi], bf[bj][sel], bf[bj][sel + 2]);
                }
        }
        __syncthreads();
    }

    const float* bias = z ? b1 : b0;
    int colb = bn + warp_n * 32 + (lane & 3) * 2;
    int rowb = bm + warp_m * 64 + (lane >> 2);
    #pragma unroll
    for (int nj = 0; nj < 4; nj++) {
        int col = colb + nj * 8;
        float2 bv = *reinterpret_cast<const float2*>(bias + col);
        #pragma unroll
        for (int mi = 0; mi < 4; mi++) {
            int r0 = rowb + mi * 16;
            if (z == 0) {
                if (r0 < NN) {
                    __half2 ho = __floats2half2_rn(d[mi][nj][0] + bv.x,
                                                   d[mi][nj][1] + bv.y);
                    *reinterpret_cast<__half2*>(g_xl1h + (size_t)r0 * HD + col) = ho;
                }
                if (r0 + 8 < NN) {
                    __half2 ho = __floats2half2_rn(d[mi][nj][2] + bv.x,
                                                   d[mi][nj][3] + bv.y);
                    *reinterpret_cast<__half2*>(g_xl1h + (size_t)(r0 + 8) * HD + col) = ho;
                }
            } else {
                if (r0 < NN) {
                    float2 o = make_float2(d[mi][nj][0] + bv.x, d[mi][nj][1] + bv.y);
                    *reinterpret_cast<float2*>(g_xr1 + (size_t)r0 * HD + col) = o;
                }
                if (r0 + 8 < NN) {
                    float2 o = make_float2(d[mi][nj][2] + bv.x, d[mi][nj][3] + bv.y);
                    *reinterpret_cast<float2*>(g_xr1 + (size_t)(r0 + 8) * HD + col) = o;
                }
            }
        }
    }
}

/* ------ layer-1 GATv2 fused with layer-2 linear, occ-capped regs ---------- */
__global__ void __launch_bounds__(256, 3)
k_gat1(const float* __restrict__ xr,
       const float* __restrict__ att, const float* __restrict__ bias,
       const float* __restrict__ bl, const float* __restrict__ br_,
       float* __restrict__ xl2, float* __restrict__ xr2)
{
    __shared__ __align__(16) float hsm[4][HD];
    __shared__ float2 part[4][16];

    int tid = threadIdx.x;
    int nl = tid >> 6;
    int node = blockIdx.x * 4 + nl;
    int u = tid & 63;

    const ulonglong2* xrp = reinterpret_cast<const ulonglong2*>(xr);
    const ulonglong2* atp = reinterpret_cast<const ulonglong2*>(att);
    const uint4* xlp = reinterpret_cast<const uint4*>(g_xl1h);

    ulonglong2 x01 = xrp[(size_t)node * 128 + u * 2];
    ulonglong2 x23 = xrp[(size_t)node * 128 + u * 2 + 1];
    u64 xp[4] = {x01.x, x01.y, x23.x, x23.y};

    ulonglong2 a01 = atp[u * 2];
    ulonglong2 a23 = atp[u * 2 + 1];
    u64 araw[4] = {a01.x, a01.y, a23.x, a23.y};
    u64 a6[4], a4[4];
    const u64 c6 = pk2(0.6f, 0.6f), c4 = pk2(0.4f, 0.4f);
    #pragma unroll
    for (int j = 0; j < 4; j++) { a6[j] = mul2(araw[j], c6); a4[j] = mul2(araw[j], c4); }

    int jb = node ? g_wp[node - 1] : 0;
    int je = g_wp[node];
    int rem = je - jb;

    float m = -1e30f, s = 0.f;
    u64 acc[4] = {0ull, 0ull, 0ull, 0ull};

    uint4 v0, v1;
    if (rem >= 2) {
        int p0 = g_col[jb], p1 = g_col[jb + 1];
        v0 = xlp[(size_t)p0 * 64 + u];
        v1 = xlp[(size_t)p1 * 64 + u];
    }
    int j = jb;
    for (; j + 2 <= je; j += 2) {
        uint4 cur0 = v0, cur1 = v1;
        int left = je - (j + 2);
        if (left >= 2) {
            int p0 = g_col[j + 2], p1 = g_col[j + 3];
            v0 = xlp[(size_t)p0 * 64 + u];
            v1 = xlp[(size_t)p1 * 64 + u];
        } else if (left == 1) {
            int p0 = g_col[j + 2];
            v0 = xlp[(size_t)p0 * 64 + u];
        }

        u64 c0[4] = {h2f2(cur0.x), h2f2(cur0.y), h2f2(cur0.z), h2f2(cur0.w)};
        u64 c1[4] = {h2f2(cur1.x), h2f2(cur1.y), h2f2(cur1.z), h2f2(cur1.w)};

        u64 e20 = 0ull, e21 = 0ull;
        #pragma unroll
        for (int q = 0; q < 4; q++) {
            u64 t0 = add2(c0[q], xp[q]);
            u64 t1 = add2(c1[q], xp[q]);
            fma2(e20, a6[q], t0);
            fma2(e21, a6[q], t1);
            fma2(e20, a4[q], t0 & ABS2);
            fma2(e21, a4[q], t1 & ABS2);
        }
        float2 f0 = upk2(e20), f1 = upk2(e21);
        float e0 = f0.x + f0.y, e1 = f1.x + f1.y;
        e0 += __shfl_xor_sync(0xffffffffu, e0, 1, 8);
        e1 += __shfl_xor_sync(0xffffffffu, e1, 1, 8);
        e0 += __shfl_xor_sync(0xffffffffu, e0, 2, 8);
        e1 += __shfl_xor_sync(0xffffffffu, e1, 2, 8);
        e0 += __shfl_xor_sync(0xffffffffu, e0, 4, 8);
        e1 += __shfl_xor_sync(0xffffffffu, e1, 4, 8);

        float nm = fmaxf(m, fmaxf(e0, e1));
        float sc = __expf(m - nm);
        float w0 = __expf(e0 - nm);
        float w1 = __expf(e1 - nm);
        s = s * sc + w0 + w1;
        u64 scp = pk2(sc, sc), w0p = pk2(w0, w0), w1p = pk2(w1, w1);
        #pragma unroll
        for (int q = 0; q < 4; q++) {
            acc[q] = mul2(acc[q], scp);
            fma2(acc[q], w0p, c0[q]);
            fma2(acc[q], w1p, c1[q]);
        }
        m = nm;
    }
    if (rem & 1) {
        uint4 cur;
        if (rem == 1) { int p0 = g_col[jb]; cur = xlp[(size_t)p0 * 64 + u]; }
        else cur = v0;
        u64 c0[4] = {h2f2(cur.x), h2f2(cur.y), h2f2(cur.z), h2f2(cur.w)};
        u64 e20 = 0ull;
        #pragma unroll
        for (int q = 0; q < 4; q++) {
            u64 t0 = add2(c0[q], xp[q]);
            fma2(e20, a6[q], t0);
            fma2(e20, a4[q], t0 & ABS2);
        }
        float2 f0 = upk2(e20);
        float e0 = f0.x + f0.y;
        e0 += __shfl_xor_sync(0xffffffffu, e0, 1, 8);
        e0 += __shfl_xor_sync(0xffffffffu, e0, 2, 8);
        e0 += __shfl_xor_sync(0xffffffffu, e0, 4, 8);
        float nm = fmaxf(m, e0);
        float sc = __expf(m - nm);
        float w0 = __expf(e0 - nm);
        s = s * sc + w0;
        u64 scp = pk2(sc, sc), w0p = pk2(w0, w0);
        #pragma unroll
        for (int q = 0; q < 4; q++) {
            acc[q] = mul2(acc[q], scp);
            fma2(acc[q], w0p, c0[q]);
        }
        m = nm;
    }

    float4 bv0 = reinterpret_cast<const float4*>(bias)[u * 2];
    float4 bv1 = reinterpret_cast<const float4*>(bias)[u * 2 + 1];
    float inv = 1.f / s;
    float2 r0 = upk2(acc[0]), r1 = upk2(acc[1]);
    float2 r2 = upk2(acc[2]), r3 = upk2(acc[3]);
    float4 o0, o1;
    o0.x = fmaxf(r0.x * inv + bv0.x, 0.f);
    o0.y = fmaxf(r0.y * inv + bv0.y, 0.f);
    o0.z = fmaxf(r1.x * inv + bv0.z, 0.f);
    o0.w = fmaxf(r1.y * inv + bv0.w, 0.f);
    o1.x = fmaxf(r2.x * inv + bv1.x, 0.f);
    o1.y = fmaxf(r2.y * inv + bv1.y, 0.f);
    o1.z = fmaxf(r3.x * inv + bv1.z, 0.f);
    o1.w = fmaxf(r3.y * inv + bv1.w, 0.f);

    float4* hs4 = reinterpret_cast<float4*>(hsm[nl]);
    hs4[u * 2] = o0;
    hs4[u * 2 + 1] = o1;
    __syncthreads();

    /* fused layer-2 linear: warp pair per node, split-k quarters */
    int wid = tid >> 5, lane = tid & 31;
    int n2 = wid >> 1;
    int qk = ((wid & 1) << 1) | (lane >> 4);
    int c = lane & 15;

    const u64* wp = reinterpret_cast<const u64*>(g_Wt2) + c;
    const float* hrow = hsm[n2];
    u64 acc2 = 0ull;
    int k0 = qk * 128;
    #pragma unroll 8
    for (int k = k0; k < k0 + 128; k++) {
        float hv = hrow[k];
        fma2(acc2, pk2(hv, hv), wp[(size_t)k * 16]);
    }
    float2 f = upk2(acc2);
    f.x += __shfl_xor_sync(0xffffffffu, f.x, 16);
    f.y += __shfl_xor_sync(0xffffffffu, f.y, 16);
    if ((wid & 1) == 1 && lane < 16) part[n2][c] = f;
    __syncthreads();
    if ((wid & 1) == 0 && lane < 16) {
        float2 p2 = part[n2][c];
        float rx = f.x + p2.x, ry = f.y + p2.y;
        int g = blockIdx.x * 4 + n2;
        int col = 2 * c;
        if (col < 16) {
            xl2[(size_t)g * NC + col]     = rx + bl[col];
            xl2[(size_t)g * NC + col + 1] = ry + bl[col + 1];
        } else {
            int cc = col - 16;
            xr2[(size_t)g * NC + cc]     = rx + br_[cc];
            xr2[(size_t)g * NC + cc + 1] = ry + br_[cc + 1];
        }
    }
}

/* --------------------- layer-2 GATv2: 4 lanes/node ------------------------ */
__global__ void __launch_bounds__(256)
k_gat2(const float* __restrict__ xl, const float* __restrict__ xr,
       const float* __restrict__ att, const float* __restrict__ bias,
       float* __restrict__ out)
{
    int tid = threadIdx.x;
    int node = blockIdx.x * 64 + (tid >> 2);
    int q = tid & 3;
    if (node >= NN) return;

    const float4* xlp = reinterpret_cast<const float4*>(xl);
    float4 xrv = reinterpret_cast<const float4*>(xr)[(size_t)node * 4 + q];
    float4 avr = reinterpret_cast<const float4*>(att)[q];
    float4 a6 = make_float4(avr.x * 0.6f, avr.y * 0.6f, avr.z * 0.6f, avr.w * 0.6f);
    float4 a4 = make_float4(avr.x * 0.4f, avr.y * 0.4f, avr.z * 0.4f, avr.w * 0.4f);

    int jb = node ? g_wp[node - 1] : 0;
    int je = g_wp[node];

    float m = -1e30f, s = 0.f;
    float4 acc = make_float4(0.f, 0.f, 0.f, 0.f);

    int j = jb;
    for (; j + 2 <= je; j += 2) {
        int s0 = g_col[j], s1 = g_col[j + 1];
        float4 c0 = xlp[(size_t)s0 * 4 + q];
        float4 c1 = xlp[(size_t)s1 * 4 + q];
        float4 t0, t1;
        t0.x = c0.x + xrv.x; t0.y = c0.y + xrv.y; t0.z = c0.z + xrv.z; t0.w = c0.w + xrv.w;
        t1.x = c1.x + xrv.x; t1.y = c1.y + xrv.y; t1.z = c1.z + xrv.z; t1.w = c1.w + xrv.w;
        float e0 = fmaf(a4.x, fabsf(t0.x), a6.x * t0.x);
        e0 = fmaf(a6.y, t0.y, fmaf(a4.y, fabsf(t0.y), e0));
        e0 = fmaf(a6.z, t0.z, fmaf(a4.z, fabsf(t0.z), e0));
        e0 = fmaf(a6.w, t0.w, fmaf(a4.w, fabsf(t0.w), e0));
        float e1 = fmaf(a4.x, fabsf(t1.x), a6.x * t1.x);
        e1 = fmaf(a6.y, t1.y, fmaf(a4.y, fabsf(t1.y), e1));
        e1 = fmaf(a6.z, t1.z, fmaf(a4.z, fabsf(t1.z), e1));
        e1 = fmaf(a6.w, t1.w, fmaf(a4.w, fabsf(t1.w), e1));
        e0 += __shfl_xor_sync(0xffffffffu, e0, 1, 4);
        e1 += __shfl_xor_sync(0xffffffffu, e1, 1, 4);
        e0 += __shfl_xor_sync(0xffffffffu, e0, 2, 4);
        e1 += __shfl_xor_sync(0xffffffffu, e1, 2, 4);

        float nm = fmaxf(m, fmaxf(e0, e1));
        float sc = __expf(m - nm);
        float w0 = __expf(e0 - nm);
        float w1 = __expf(e1 - nm);
        s = s * sc + w0 + w1;
        acc.x = fmaf(w1, c1.x, fmaf(w0, c0.x, acc.x * sc));
        acc.y = fmaf(w1, c1.y, fmaf(w0, c0.y, acc.y * sc));
        acc.z = fmaf(w1, c1.z, fmaf(w0, c0.z, acc.z * sc));
        acc.w = fmaf(w1, c1.w, fmaf(w0, c0.w, acc.w * sc));
        m = nm;
    }
    for (; j < je; j++) {
        int s0 = g_col[j];
        float4 c0 = xlp[(size_t)s0 * 4 + q];
        float4 t0;
        t0.x = c0.x + xrv.x; t0.y = c0.y + xrv.y; t0.z = c0.z + xrv.z; t0.w = c0.w + xrv.w;
        float e0 = fmaf(a4.x, fabsf(t0.x), a6.x * t0.x);
        e0 = fmaf(a6.y, t0.y, fmaf(a4.y, fabsf(t0.y), e0));
        e0 = fmaf(a6.z, t0.z, fmaf(a4.z, fabsf(t0.z), e0));
        e0 = fmaf(a6.w, t0.w, fmaf(a4.w, fabsf(t0.w), e0));
        e0 += __shfl_xor_sync(0xffffffffu, e0, 1, 4);
        e0 += __shfl_xor_sync(0xffffffffu, e0, 2, 4);
        float nm = fmaxf(m, e0);
        float sc = __expf(m - nm);
        float w0 = __expf(e0 - nm);
        s = s * sc + w0;
        acc.x = fmaf(w0, c0.x, acc.x * sc);
        acc.y = fmaf(w0, c0.y, acc.y * sc);
        acc.z = fmaf(w0, c0.z, acc.z * sc);
        acc.w = fmaf(w0, c0.w, acc.w * sc);
        m = nm;
    }

    float inv = 1.f / s;
    float4 bvq = reinterpret_cast<const float4*>(bias)[q];
    float4 o;
    o.x = acc.x * inv + bvq.x;
    o.y = acc.y * inv + bvq.y;
    o.z = acc.z * inv + bvq.z;
    o.w = acc.w * inv + bvq.w;
    reinterpret_cast<float4*>(out)[(size_t)node * 4 + q] = o;
}

/* ------------------------------- launch ---------------------------------- */
extern "C" void kernel_launch(void* const* d_in, const int* in_sizes, int n_in,
                              void* d_out, int out_size)
{
    const float* x     = (const float*)d_in[0];
    const void*  ei    = d_in[1];
    const float* W_l1  = (const float*)d_in[2];
    const float* b_l1  = (const float*)d_in[3];
    const float* W_r1  = (const float*)d_in[4];
    const float* b_r1  = (const float*)d_in[5];
    const float* att1  = (const float*)d_in[6];
    const float* bias1 = (const float*)d_in[7];
    const float* W_l2  = (const float*)d_in[8];
    const float* b_l2  = (const float*)d_in[9];
    const float* W_r2  = (const float*)d_in[10];
    const float* b_r2  = (const float*)d_in[11];
    const float* att2  = (const float*)d_in[12];
    const float* bias2 = (const float*)d_in[13];
    float* out = (float*)d_out;

    static cudaStream_t s2 = 0;
    static cudaEvent_t evA = 0, evB = 0;
    if (s2 == 0) {
        cudaStreamCreateWithFlags(&s2, cudaStreamNonBlocking);
        cudaEventCreateWithFlags(&evA, cudaEventDisableTiming);
        cudaEventCreateWithFlags(&evB, cudaEventDisableTiming);
    }

    float *xr1, *xl2, *xr2;
    cudaGetSymbolAddress((void**)&xr1, g_xr1);
    cudaGetSymbolAddress((void**)&xl2, g_xl2);
    cudaGetSymbolAddress((void**)&xr2, g_xr2);

    cudaFuncSetAttribute(k_hmma, cudaFuncAttributeMaxDynamicSharedMemorySize, 6 * STG + 1024);

    k_prep0<<<NB0 + NBS + 1, 256>>>(x, W_l1, W_r1, W_l2, W_r2, (const int*)ei);
    cudaEventRecord(evA, 0);

    /* CSR branch on side stream, concurrent with hmma */
    cudaStreamWaitEvent(s2, evA, 0);
    k_hist<<<(ET + 255) / 256, 256, 0, s2>>>(ei);
    k_scanA<<<NBS, 256, 0, s2>>>();
    k_scanB<<<1, 1024, 0, s2>>>();
    k_scatter<<<(ET + 255) / 256, 256, 0, s2>>>(ei);
    cudaEventRecord(evB, s2);

    /* GEMM branch on main stream */
    dim3 gm(NNP / 128, HD / 128, 2);
    k_hmma<<<gm, 256, 6 * STG + 1024>>>(b_l1, b_r1);

    cudaStreamWaitEvent(0, evB, 0);
    k_gat1<<<NN / 4, 256>>>(xr1, att1, bias1, b_l2, b_r2, xl2, xr2);
    k_gat2<<<(NN + 63) / 64, 256>>>(xl2, xr2, att2, bias2, out);
}

// round 16
// speedup vs baseline: 1.2305x; 1.0590x over previous
#include <cuda_runtime.h>
#include <cuda_fp16.h>
#include <cstdint>

#define NN 20000
#define NNP 20096
#define NE 320000
#define ET 340000
#define F1 256
#define KK2 512
#define HD 512
#define NC 16
#define NBS 79

/* ----------------------------- device scratch ---------------------------- */
__device__ __half g_xl1h[(size_t)NN * HD];
__device__ float g_xr1[NN * HD];
__device__ float g_xl2[NN * NC];
__device__ float g_xr2[NN * NC];
__device__ float g_Wt2[HD * 32];
__device__ __half g_Ahf[(size_t)NNP * KK2];
__device__ __half g_Bhf[2 * HD * KK2];
__device__ int   g_deg[NN];
__device__ int   g_wp[NN];
__device__ int   g_bsum[96];
__device__ int   g_col[ET];
__device__ int   g_is64;

/* --------------------------- helpers ------------------------------------- */
typedef unsigned long long u64;

__device__ __forceinline__ u64 pk2(float x, float y) {
    u64 r;
    asm("mov.b64 %0, {%1, %2};" : "=l"(r)
        : "r"(__float_as_uint(x)), "r"(__float_as_uint(y)));
    return r;
}
__device__ __forceinline__ void fma2(u64& c, u64 a, u64 b) {
    asm("fma.rn.f32x2 %0, %1, %2, %0;" : "+l"(c) : "l"(a), "l"(b));
}
__device__ __forceinline__ u64 add2(u64 a, u64 b) {
    u64 r; asm("add.rn.f32x2 %0, %1, %2;" : "=l"(r) : "l"(a), "l"(b)); return r;
}
__device__ __forceinline__ u64 mul2(u64 a, u64 b) {
    u64 r; asm("mul.rn.f32x2 %0, %1, %2;" : "=l"(r) : "l"(a), "l"(b)); return r;
}
__device__ __forceinline__ float2 upk2(u64 v) {
    unsigned lo, hi;
    asm("mov.b64 {%0, %1}, %2;" : "=r"(lo), "=r"(hi) : "l"(v));
    return make_float2(__uint_as_float(lo), __uint_as_float(hi));
}
__device__ __forceinline__ u64 h2f2(uint32_t h) {
    __half2 hv = *reinterpret_cast<__half2*>(&h);
    float2 f = __half22float2(hv);
    return pk2(f.x, f.y);
}

__device__ __forceinline__ int edge_val(const void* ei, int idx) {
    if (g_is64) return (int)(((const long long*)ei)[idx]);
    return ((const int*)ei)[idx];
}

__device__ __forceinline__ uint32_t smem_u32(const void* p) {
    uint32_t a;
    asm("{ .reg .u64 t; cvta.to.shared.u64 t, %1; cvt.u32.u64 %0, t; }"
        : "=r"(a) : "l"(p));
    return a;
}

__device__ __forceinline__ void cpa16(uint32_t dst, const void* src) {
    asm volatile("cp.async.cg.shared.global [%0], [%1], 16;"
                 :: "r"(dst), "l"(src) : "memory");
}
#define CPA_COMMIT() asm volatile("cp.async.commit_group;" ::: "memory")
#define CPA_WAIT(n)  asm volatile("cp.async.wait_group %0;" :: "n"(n) : "memory")

static __device__ __forceinline__ uint32_t sw128(uint32_t off) {
    return off ^ ((off >> 3) & 0x70);
}

#define LDSM4(r0, r1, r2, r3, a) \
    asm volatile("ldmatrix.sync.aligned.m8n8.x4.shared.b16 {%0,%1,%2,%3}, [%4];" \
                 : "=r"(r0), "=r"(r1), "=r"(r2), "=r"(r3) : "r"(a))

__device__ __forceinline__ void mma16816(float* d, const uint32_t* a,
                                         uint32_t b0, uint32_t b1) {
    asm volatile(
        "mma.sync.aligned.m16n8k16.row.col.f32.f16.f16.f32 "
        "{%0,%1,%2,%3}, {%4,%5,%6,%7}, {%8,%9}, {%0,%1,%2,%3};"
        : "+f"(d[0]), "+f"(d[1]), "+f"(d[2]), "+f"(d[3])
        : "r"(a[0]), "r"(a[1]), "r"(a[2]), "r"(a[3]), "r"(b0), "r"(b1));
}

#define ABS2 0x7FFFFFFF7FFFFFFFull

/* ------ prep0: A split + B convert + W2 transpose + deg zero + detect ----- */
#define W_A (NNP * (F1 / 4))
#define W_B (2 * HD * F1)
#define W_W (HD * NC)
#define NB0 ((W_A + W_B + W_W + 255) / 256)

__global__ void k_prep0(const float* __restrict__ x,
                        const float* __restrict__ W0, const float* __restrict__ W1,
                        const float* __restrict__ Wl2, const float* __restrict__ Wr2,
                        const int* __restrict__ ei32)
{
    if (blockIdx.x >= NB0) {
        int b = blockIdx.x - NB0;
        if (b < NBS) {
            int i = b * 256 + threadIdx.x;
            if (i < NN) g_deg[i] = 0;
        } else {
            __shared__ int sflag;
            int tid = threadIdx.x;
            if (tid == 0) sflag = 0;
            __syncthreads();
            int bad = 0;
            #pragma unroll
            for (int i = 0; i < 4; i++) bad |= ei32[(tid * 4 + i) * 2 + 1];
            if (bad) atomicOr(&sflag, 1);
            __syncthreads();
            if (tid == 0) g_is64 = (sflag == 0) ? 1 : 0;
        }
        return;
    }

    int idx = blockIdx.x * 256 + threadIdx.x;
    if (idx < W_A) {
        int i = idx;
        int m = i >> 6;
        int c4 = i & 63;
        float4 v = make_float4(0.f, 0.f, 0.f, 0.f);
        if (m < NN) v = reinterpret_cast<const float4*>(x)[i];
        __half hx = __float2half_rn(v.x);
        __half hy = __float2half_rn(v.y);
        __half hz = __float2half_rn(v.z);
        __half hw = __float2half_rn(v.w);
        __half lx = __float2half_rn(v.x - __half2float(hx));
        __half ly = __float2half_rn(v.y - __half2float(hy));
        __half lz = __float2half_rn(v.z - __half2float(hz));
        __half lw = __float2half_rn(v.w - __half2float(hw));
        __half2 h01, h23, l01, l23;
        h01.x = hx; h01.y = hy; h23.x = hz; h23.y = hw;
        l01.x = lx; l01.y = ly; l23.x = lz; l23.y = lw;
        size_t rb = (size_t)m * KK2 + c4 * 4;
        __half2* p0 = reinterpret_cast<__half2*>(&g_Ahf[rb]);
        __half2* p1 = reinterpret_cast<__half2*>(&g_Ahf[rb + F1]);
        p0[0] = h01; p0[1] = h23;
        p1[0] = l01; p1[1] = l23;
    } else if (idx < W_A + W_B) {
        int i = idx - W_A;
        int z = i >> 17;
        int r = i & 131071;
        int n = r >> 8, k = r & 255;
        const float* W = z ? W1 : W0;
        float v = W[(size_t)k * HD + n];
        __half h = __float2half_rn(v);
        size_t base = (size_t)z * HD * KK2 + (size_t)n * KK2;
        g_Bhf[base + k] = h;
        g_Bhf[base + F1 + k] = h;
    } else if (idx < W_A + W_B + W_W) {
        int i = idx - W_A - W_B;
        int k = i >> 4, c = i & 15;
        g_Wt2[k * 32 + c]      = Wl2[i];
        g_Wt2[k * 32 + 16 + c] = Wr2[i];
    }
}

/* ------------------------------- CSR build ------------------------------- */
__global__ void k_hist(const void* __restrict__ ei) {
    int i = blockIdx.x * blockDim.x + threadIdx.x;
    if (i >= ET) return;
    int dst = (i < NE) ? edge_val(ei, NE + i) : (i - NE);
    atomicAdd(&g_deg[dst], 1);
}

__global__ void __launch_bounds__(256) k_scanA() {
    __shared__ int wsum[8];
    int b = blockIdx.x, tid = threadIdx.x, lane = tid & 31, wid = tid >> 5;
    int i = b * 256 + tid;
    int v = (i < NN) ? g_deg[i] : 0;
    int x = v;
    #pragma unroll
    for (int off = 1; off < 32; off <<= 1) {
        int t = __shfl_up_sync(0xffffffffu, x, off);
        if (lane >= off) x += t;
    }
    if (lane == 31) wsum[wid] = x;
    __syncthreads();
    if (wid == 0 && lane < 8) {
        int y = wsum[lane];
        #pragma unroll
        for (int off = 1; off < 8; off <<= 1) {
            int t = __shfl_up_sync(0x000000ffu, y, off, 8);
            if (lane >= off) y += t;
        }
        wsum[lane] = y;
    }
    __syncthreads();
    int base = wid ? wsum[wid - 1] : 0;
    int incl = base + x;
    if (i < NN) g_wp[i] = incl - v;
    if (tid == 255) g_bsum[b] = wsum[7];
}

__global__ void __launch_bounds__(1024) k_scanB() {
    __shared__ int off[NBS + 1];
    int tid = threadIdx.x, lane = tid & 31, wid = tid >> 5;
    if (wid == 0) {
        int carry = 0;
        #pragma unroll
        for (int c = 0; c < 3; c++) {
            int idx = c * 32 + lane;
            int v = (idx < NBS) ? g_bsum[idx] : 0;
            int x = v;
            #pragma unroll
            for (int o = 1; o < 32; o <<= 1) {
                int t = __shfl_up_sync(0xffffffffu, x, o);
                if (lane >= o) x += t;
            }
            if (idx < NBS) off[idx] = carry + x - v;
            carry += __shfl_sync(0xffffffffu, x, 31);
        }
    }
    __syncthreads();
    for (int i = tid; i < NN; i += 1024) g_wp[i] += off[i >> 8];
}

__global__ void k_scatter(const void* __restrict__ ei) {
    int i = blockIdx.x * blockDim.x + threadIdx.x;
    if (i >= ET) return;
    int src, dst;
    if (i < NE) { src = edge_val(ei, i); dst = edge_val(ei, NE + i); }
    else        { src = i - NE; dst = i - NE; }
    int pos = atomicAdd(&g_wp[dst], 1);
    g_col[pos] = src;
}
/* after k_scatter: g_wp[n] == row_end(n) == row_start(n+1) */

/* -------------------- 2xFP16 HMMA GEMM, 3-stage, 2 CTA/SM ----------------- */
#define BK 64
#define NIT (KK2 / BK)
#define STG 16384

__global__ void __launch_bounds__(256, 2)
k_hmma(const float* __restrict__ b0, const float* __restrict__ b1)
{
    extern __shared__ char dyn[];
    uint32_t SB = (smem_u32(dyn) + 1023u) & ~1023u;

    int tid = threadIdx.x;
    int lane = tid & 31, wid = tid >> 5;
    int warp_m = wid >> 2, warp_n = wid & 3;
    int bm = blockIdx.x * 128;
    int bn = blockIdx.y * 128;
    int z  = blockIdx.z;

    const __half* Asrc = g_Ahf + (size_t)bm * KK2;
    const __half* Bsrc = g_Bhf + (size_t)z * HD * KK2 + (size_t)bn * KK2;

    int lr = tid >> 1;
    int lc = (tid & 1) << 2;
    auto load_tiles = [&](int it, int s) {
        int k0 = it * BK;
        uint32_t Ab = SB + (uint32_t)s * (2 * STG);
        uint32_t Bb = Ab + STG;
        #pragma unroll
        for (int i = 0; i < 4; i++) {
            int cj = lc + i;
            cpa16(Ab + sw128((uint32_t)(lr * 128 + cj * 16)),
                  Asrc + (size_t)lr * KK2 + k0 + cj * 8);
            cpa16(Bb + sw128((uint32_t)(lr * 128 + cj * 16)),
                  Bsrc + (size_t)lr * KK2 + k0 + cj * 8);
        }
        CPA_COMMIT();
    };

    float d[4][4][4];
    #pragma unroll
    for (int i = 0; i < 4; i++)
        #pragma unroll
        for (int j = 0; j < 4; j++)
            #pragma unroll
            for (int q = 0; q < 4; q++) d[i][j][q] = 0.f;

    load_tiles(0, 0);
    load_tiles(1, 1);

    int l15 = lane & 15;
    int kb_lane = (lane & 16);

    #pragma unroll 1
    for (int it = 0; it < NIT; it++) {
        if (it + 1 < NIT) { CPA_WAIT(1); } else { CPA_WAIT(0); }
        __syncthreads();
        if (it + 2 < NIT) load_tiles(it + 2, (it + 2) % 3);

        uint32_t Ab = SB + (uint32_t)(it % 3) * (2 * STG);
        uint32_t Bb = Ab + STG;

        #pragma unroll
        for (int ks = 0; ks < 4; ks++) {
            uint32_t a[4][4];
            #pragma unroll
            for (int mi = 0; mi < 4; mi++) {
                uint32_t off = (uint32_t)((warp_m * 64 + mi * 16 + l15) * 128
                                          + ks * 32 + kb_lane);
                LDSM4(a[mi][0], a[mi][1], a[mi][2], a[mi][3], Ab + sw128(off));
            }
            uint32_t bf[2][4];
            #pragma unroll
            for (int bj = 0; bj < 2; bj++) {
                uint32_t off = (uint32_t)((warp_n * 32 + bj * 16 + l15) * 128
                                          + ks * 32 + kb_lane);
                LDSM4(bf[bj][0], bf[bj][1], bf[bj][2], bf[bj][3], Bb + sw128(off));
            }
            #pragma unroll
            for (int mi = 0; mi < 4; mi++)
                #pragma unroll
                for (int nj = 0; nj < 4; nj++) {
                    int bj = nj >> 1, sel = nj & 1;
                    mma16816(d[mi][nj], a[mi], bf[bj][sel], bf[bj][sel + 2]);
                }
        }
        __syncthreads();
    }

    const float* bias = z ? b1 : b0;
    int colb = bn + warp_n * 32 + (lane & 3) * 2;
    int rowb = bm + warp_m * 64 + (lane >> 2);
    #pragma unroll
    for (int nj = 0; nj < 4; nj++) {
        int col = colb + nj * 8;
        float2 bv = *reinterpret_cast<const float2*>(bias + col);
        #pragma unroll
        for (int mi = 0; mi < 4; mi++) {
            int r0 = rowb + mi * 16;
            if (z == 0) {
                if (r0 < NN) {
                    __half2 ho = __floats2half2_rn(d[mi][nj][0] + bv.x,
                                                   d[mi][nj][1] + bv.y);
                    *reinterpret_cast<__half2*>(g_xl1h + (size_t)r0 * HD + col) = ho;
                }
                if (r0 + 8 < NN) {
                    __half2 ho = __floats2half2_rn(d[mi][nj][2] + bv.x,
                                                   d[mi][nj][3] + bv.y);
                    *reinterpret_cast<__half2*>(g_xl1h + (size_t)(r0 + 8) * HD + col) = ho;
                }
            } else {
                if (r0 < NN) {
                    float2 o = make_float2(d[mi][nj][0] + bv.x, d[mi][nj][1] + bv.y);
                    *reinterpret_cast<float2*>(g_xr1 + (size_t)r0 * HD + col) = o;
                }
                if (r0 + 8 < NN) {
                    float2 o = make_float2(d[mi][nj][2] + bv.x, d[mi][nj][3] + bv.y);
                    *reinterpret_cast<float2*>(g_xr1 + (size_t)(r0 + 8) * HD + col) = o;
                }
            }
        }
    }
}

/* ------ layer-1 GATv2 + fused layer-2 linear, cp.async gather ring -------- */
/* lane u of node owns dims [8u,8u+8); ring: 3 pair-slots x 2 edges x 1KB/node */
__global__ void __launch_bounds__(256, 3)
k_gat1(const float* __restrict__ xr,
       const float* __restrict__ att, const float* __restrict__ bias,
       const float* __restrict__ bl, const float* __restrict__ br_,
       float* __restrict__ xl2, float* __restrict__ xr2)
{
    __shared__ __align__(16) float hsm[4][HD];
    __shared__ float2 part[4][16];
    __shared__ __align__(16) uint4 ring[4 * 3 * 2 * 64];   /* 24KB */

    int tid = threadIdx.x;
    int nl = tid >> 6;
    int node = blockIdx.x * 4 + nl;
    int u = tid & 63;

    const ulonglong2* xrp = reinterpret_cast<const ulonglong2*>(xr);
    const ulonglong2* atp = reinterpret_cast<const ulonglong2*>(att);
    const __half* xlb = g_xl1h;

    ulonglong2 x01 = xrp[(size_t)node * 128 + u * 2];
    ulonglong2 x23 = xrp[(size_t)node * 128 + u * 2 + 1];
    u64 xp[4] = {x01.x, x01.y, x23.x, x23.y};

    ulonglong2 a01 = atp[u * 2];
    ulonglong2 a23 = atp[u * 2 + 1];
    u64 araw[4] = {a01.x, a01.y, a23.x, a23.y};
    u64 a6[4], a4[4];
    const u64 c6 = pk2(0.6f, 0.6f), c4 = pk2(0.4f, 0.4f);
    #pragma unroll
    for (int j = 0; j < 4; j++) { a6[j] = mul2(araw[j], c6); a4[j] = mul2(araw[j], c4); }

    int jb = node ? g_wp[node - 1] : 0;
    int je = g_wp[node];
    int rem = je - jb;
    int np = rem >> 1;            /* full pairs */

    /* ring addressing: slot s, edge e -> ring[((nl*3+s)*2+e)*64 + u] */
    uint32_t rb0 = smem_u32(ring) + ((uint32_t)nl * 6 + 0) * 1024u + (uint32_t)u * 16u;
    const uint4* rptr = ring + (nl * 6) * 64 + u;

    /* prologue: issue up to 3 pair groups (empty commits keep count) */
    #pragma unroll
    for (int p = 0; p < 3; p++) {
        if (p < np) {
            int s0 = g_col[jb + 2 * p], s1 = g_col[jb + 2 * p + 1];
            cpa16(rb0 + (uint32_t)(p * 2 + 0) * 1024u, xlb + (size_t)s0 * HD + u * 8);
            cpa16(rb0 + (uint32_t)(p * 2 + 1) * 1024u, xlb + (size_t)s1 * HD + u * 8);
        }
        CPA_COMMIT();
    }

    float m = -1e30f, s = 0.f;
    u64 acc[4] = {0ull, 0ull, 0ull, 0ull};

    for (int p = 0; p < np; p++) {
        CPA_WAIT(2);
        int sl = p - (p / 3) * 3;
        uint4 cur0 = rptr[(sl * 2 + 0) * 64];
        uint4 cur1 = rptr[(sl * 2 + 1) * 64];

        if (p + 3 < np) {
            int s0 = g_col[jb + 2 * (p + 3)], s1 = g_col[jb + 2 * (p + 3) + 1];
            int sn = (p + 3) - ((p + 3) / 3) * 3;
            cpa16(rb0 + (uint32_t)(sn * 2 + 0) * 1024u, xlb + (size_t)s0 * HD + u * 8);
            cpa16(rb0 + (uint32_t)(sn * 2 + 1) * 1024u, xlb + (size_t)s1 * HD + u * 8);
        }
        CPA_COMMIT();

        u64 c0[4] = {h2f2(cur0.x), h2f2(cur0.y), h2f2(cur0.z), h2f2(cur0.w)};
        u64 c1[4] = {h2f2(cur1.x), h2f2(cur1.y), h2f2(cur1.z), h2f2(cur1.w)};

        u64 e20 = 0ull, e21 = 0ull;
        #pragma unroll
        for (int q = 0; q < 4; q++) {
            u64 t0 = add2(c0[q], xp[q]);
            u64 t1 = add2(c1[q], xp[q]);
            fma2(e20, a6[q], t0);
            fma2(e21, a6[q], t1);
            fma2(e20, a4[q], t0 & ABS2);
            fma2(e21, a4[q], t1 & ABS2);
        }
        float2 f0 = upk2(e20), f1 = upk2(e21);
        float e0 = f0.x + f0.y, e1 = f1.x + f1.y;
        e0 += __shfl_xor_sync(0xffffffffu, e0, 1, 8);
        e1 += __shfl_xor_sync(0xffffffffu, e1, 1, 8);
        e0 += __shfl_xor_sync(0xffffffffu, e0, 2, 8);
        e1 += __shfl_xor_sync(0xffffffffu, e1, 2, 8);
        e0 += __shfl_xor_sync(0xffffffffu, e0, 4, 8);
        e1 += __shfl_xor_sync(0xffffffffu, e1, 4, 8);

        float nm = fmaxf(m, fmaxf(e0, e1));
        float sc = __expf(m - nm);
        float w0 = __expf(e0 - nm);
        float w1 = __expf(e1 - nm);
        s = s * sc + w0 + w1;
        u64 scp = pk2(sc, sc), w0p = pk2(w0, w0), w1p = pk2(w1, w1);
        #pragma unroll
        for (int q = 0; q < 4; q++) {
            acc[q] = mul2(acc[q], scp);
            fma2(acc[q], w0p, c0[q]);
            fma2(acc[q], w1p, c1[q]);
        }
        m = nm;
    }
    if (rem & 1) {
        int s0 = g_col[je - 1];
        uint4 cur = reinterpret_cast<const uint4*>(xlb + (size_t)s0 * HD)[u];
        u64 c0[4] = {h2f2(cur.x), h2f2(cur.y), h2f2(cur.z), h2f2(cur.w)};
        u64 e20 = 0ull;
        #pragma unroll
        for (int q = 0; q < 4; q++) {
            u64 t0 = add2(c0[q], xp[q]);
            fma2(e20, a6[q], t0);
            fma2(e20, a4[q], t0 & ABS2);
        }
        float2 f0 = upk2(e20);
        float e0 = f0.x + f0.y;
        e0 += __shfl_xor_sync(0xffffffffu, e0, 1, 8);
        e0 += __shfl_xor_sync(0xffffffffu, e0, 2, 8);
        e0 += __shfl_xor_sync(0xffffffffu, e0, 4, 8);
        float nm = fmaxf(m, e0);
        float sc = __expf(m - nm);
        float w0 = __expf(e0 - nm);
        s = s * sc + w0;
        u64 scp = pk2(sc, sc), w0p = pk2(w0, w0);
        #pragma unroll
        for (int q = 0; q < 4; q++) {
            acc[q] = mul2(acc[q], scp);
            fma2(acc[q], w0p, c0[q]);
        }
        m = nm;
    }

    float4 bv0 = reinterpret_cast<const float4*>(bias)[u * 2];
    float4 bv1 = reinterpret_cast<const float4*>(bias)[u * 2 + 1];
    float inv = 1.f / s;
    float2 r0 = upk2(acc[0]), r1 = upk2(acc[1]);
    float2 r2 = upk2(acc[2]), r3 = upk2(acc[3]);
    float4 o0, o1;
    o0.x = fmaxf(r0.x * inv + bv0.x, 0.f);
    o0.y = fmaxf(r0.y * inv + bv0.y, 0.f);
    o0.z = fmaxf(r1.x * inv + bv0.z, 0.f);
    o0.w = fmaxf(r1.y * inv + bv0.w, 0.f);
    o1.x = fmaxf(r2.x * inv + bv1.x, 0.f);
    o1.y = fmaxf(r2.y * inv + bv1.y, 0.f);
    o1.z = fmaxf(r3.x * inv + bv1.z, 0.f);
    o1.w = fmaxf(r3.y * inv + bv1.w, 0.f);

    float4* hs4 = reinterpret_cast<float4*>(hsm[nl]);
    hs4[u * 2] = o0;
    hs4[u * 2 + 1] = o1;
    __syncthreads();

    /* fused layer-2 linear: warp pair per node, split-k quarters */
    int wid = tid >> 5, lane = tid & 31;
    int n2 = wid >> 1;
    int qk = ((wid & 1) << 1) | (lane >> 4);
    int c = lane & 15;

    const u64* wp = reinterpret_cast<const u64*>(g_Wt2) + c;
    const float* hrow = hsm[n2];
    u64 acc2 = 0ull;
    int k0 = qk * 128;
    #pragma unroll 8
    for (int k = k0; k < k0 + 128; k++) {
        float hv = hrow[k];
        fma2(acc2, pk2(hv, hv), wp[(size_t)k * 16]);
    }
    float2 f = upk2(acc2);
    f.x += __shfl_xor_sync(0xffffffffu, f.x, 16);
    f.y += __shfl_xor_sync(0xffffffffu, f.y, 16);
    if ((wid & 1) == 1 && lane < 16) part[n2][c] = f;
    __syncthreads();
    if ((wid & 1) == 0 && lane < 16) {
        float2 p2 = part[n2][c];
        float rx = f.x + p2.x, ry = f.y + p2.y;
        int g = blockIdx.x * 4 + n2;
        int col = 2 * c;
        if (col < 16) {
            xl2[(size_t)g * NC + col]     = rx + bl[col];
            xl2[(size_t)g * NC + col + 1] = ry + bl[col + 1];
        } else {
            int cc = col - 16;
            xr2[(size_t)g * NC + cc]     = rx + br_[cc];
            xr2[(size_t)g * NC + cc + 1] = ry + br_[cc + 1];
        }
    }
}

/* --------------------- layer-2 GATv2: 4 lanes/node ------------------------ */
__global__ void __launch_bounds__(256)
k_gat2(const float* __restrict__ xl, const float* __restrict__ xr,
       const float* __restrict__ att, const float* __restrict__ bias,
       float* __restrict__ out)
{
    int tid = threadIdx.x;
    int node = blockIdx.x * 64 + (tid >> 2);
    int q = tid & 3;
    if (node >= NN) return;

    const float4* xlp = reinterpret_cast<const float4*>(xl);
    float4 xrv = reinterpret_cast<const float4*>(xr)[(size_t)node * 4 + q];
    float4 avr = reinterpret_cast<const float4*>(att)[q];
    float4 a6 = make_float4(avr.x * 0.6f, avr.y * 0.6f, avr.z * 0.6f, avr.w * 0.6f);
    float4 a4 = make_float4(avr.x * 0.4f, avr.y * 0.4f, avr.z * 0.4f, avr.w * 0.4f);

    int jb = node ? g_wp[node - 1] : 0;
    int je = g_wp[node];

    float m = -1e30f, s = 0.f;
    float4 acc = make_float4(0.f, 0.f, 0.f, 0.f);

    int j = jb;
    for (; j + 2 <= je; j += 2) {
        int s0 = g_col[j], s1 = g_col[j + 1];
        float4 c0 = xlp[(size_t)s0 * 4 + q];
        float4 c1 = xlp[(size_t)s1 * 4 + q];
        float4 t0, t1;
        t0.x = c0.x + xrv.x; t0.y = c0.y + xrv.y; t0.z = c0.z + xrv.z; t0.w = c0.w + xrv.w;
        t1.x = c1.x + xrv.x; t1.y = c1.y + xrv.y; t1.z = c1.z + xrv.z; t1.w = c1.w + xrv.w;
        float e0 = fmaf(a4.x, fabsf(t0.x), a6.x * t0.x);
        e0 = fmaf(a6.y, t0.y, fmaf(a4.y, fabsf(t0.y), e0));
        e0 = fmaf(a6.z, t0.z, fmaf(a4.z, fabsf(t0.z), e0));
        e0 = fmaf(a6.w, t0.w, fmaf(a4.w, fabsf(t0.w), e0));
        float e1 = fmaf(a4.x, fabsf(t1.x), a6.x * t1.x);
        e1 = fmaf(a6.y, t1.y, fmaf(a4.y, fabsf(t1.y), e1));
        e1 = fmaf(a6.z, t1.z, fmaf(a4.z, fabsf(t1.z), e1));
        e1 = fmaf(a6.w, t1.w, fmaf(a4.w, fabsf(t1.w), e1));
        e0 += __shfl_xor_sync(0xffffffffu, e0, 1, 4);
        e1 += __shfl_xor_sync(0xffffffffu, e1, 1, 4);
        e0 += __shfl_xor_sync(0xffffffffu, e0, 2, 4);
        e1 += __shfl_xor_sync(0xffffffffu, e1, 2, 4);

        float nm = fmaxf(m, fmaxf(e0, e1));
        float sc = __expf(m - nm);
        float w0 = __expf(e0 - nm);
        float w1 = __expf(e1 - nm);
        s = s * sc + w0 + w1;
        acc.x = fmaf(w1, c1.x, fmaf(w0, c0.x, acc.x * sc));
        acc.y = fmaf(w1, c1.y, fmaf(w0, c0.y, acc.y * sc));
        acc.z = fmaf(w1, c1.z, fmaf(w0, c0.z, acc.z * sc));
        acc.w = fmaf(w1, c1.w, fmaf(w0, c0.w, acc.w * sc));
        m = nm;
    }
    for (; j < je; j++) {
        int s0 = g_col[j];
        float4 c0 = xlp[(size_t)s0 * 4 + q];
        float4 t0;
        t0.x = c0.x + xrv.x; t0.y = c0.y + xrv.y; t0.z = c0.z + xrv.z; t0.w = c0.w + xrv.w;
        float e0 = fmaf(a4.x, fabsf(t0.x), a6.x * t0.x);
        e0 = fmaf(a6.y, t0.y, fmaf(a4.y, fabsf(t0.y), e0));
        e0 = fmaf(a6.z, t0.z, fmaf(a4.z, fabsf(t0.z), e0));
        e0 = fmaf(a6.w, t0.w, fmaf(a4.w, fabsf(t0.w), e0));
        e0 += __shfl_xor_sync(0xffffffffu, e0, 1, 4);
        e0 += __shfl_xor_sync(0xffffffffu, e0, 2, 4);
        float nm = fmaxf(m, e0);
        float sc = __expf(m - nm);
        float w0 = __expf(e0 - nm);
        s = s * sc + w0;
        acc.x = fmaf(w0, c0.x, acc.x * sc);
        acc.y = fmaf(w0, c0.y, acc.y * sc);
        acc.z = fmaf(w0, c0.z, acc.z * sc);
        acc.w = fmaf(w0, c0.w, acc.w * sc);
        m = nm;
    }

    float inv = 1.f / s;
    float4 bvq = reinterpret_cast<const float4*>(bias)[q];
    float4 o;
    o.x = acc.x * inv + bvq.x;
    o.y = acc.y * inv + bvq.y;
    o.z = acc.z * inv + bvq.z;
    o.w = acc.w * inv + bvq.w;
    reinterpret_cast<float4*>(out)[(size_t)node * 4 + q] = o;
}

/* ------------------------------- launch ---------------------------------- */
extern "C" void kernel_launch(void* const* d_in, const int* in_sizes, int n_in,
                              void* d_out, int out_size)
{
    const float* x     = (const float*)d_in[0];
    const void*  ei    = d_in[1];
    const float* W_l1  = (const float*)d_in[2];
    const float* b_l1  = (const float*)d_in[3];
    const float* W_r1  = (const float*)d_in[4];
    const float* b_r1  = (const float*)d_in[5];
    const float* att1  = (const float*)d_in[6];
    const float* bias1 = (const float*)d_in[7];
    const float* W_l2  = (const float*)d_in[8];
    const float* b_l2  = (const float*)d_in[9];
    const float* W_r2  = (const float*)d_in[10];
    const float* b_r2  = (const float*)d_in[11];
    const float* att2  = (const float*)d_in[12];
    const float* bias2 = (const float*)d_in[13];
    float* out = (float*)d_out;

    static cudaStream_t s2 = 0;
    static cudaEvent_t evA = 0, evB = 0;
    if (s2 == 0) {
        cudaStreamCreateWithFlags(&s2, cudaStreamNonBlocking);
        cudaEventCreateWithFlags(&evA, cudaEventDisableTiming);
        cudaEventCreateWithFlags(&evB, cudaEventDisableTiming);
    }

    float *xr1, *xl2, *xr2;
    cudaGetSymbolAddress((void**)&xr1, g_xr1);
    cudaGetSymbolAddress((void**)&xl2, g_xl2);
    cudaGetSymbolAddress((void**)&xr2, g_xr2);

    cudaFuncSetAttribute(k_hmma, cudaFuncAttributeMaxDynamicSharedMemorySize, 6 * STG + 1024);

    k_prep0<<<NB0 + NBS + 1, 256>>>(x, W_l1, W_r1, W_l2, W_r2, (const int*)ei);
    cudaEventRecord(evA, 0);

    cudaStreamWaitEvent(s2, evA, 0);
    k_hist<<<(ET + 255) / 256, 256, 0, s2>>>(ei);
    k_scanA<<<NBS, 256, 0, s2>>>();
    k_scanB<<<1, 1024, 0, s2>>>();
    k_scatter<<<(ET + 255) / 256, 256, 0, s2>>>(ei);
    cudaEventRecord(evB, s2);

    dim3 gm(NNP / 128, HD / 128, 2);
    k_hmma<<<gm, 256, 6 * STG + 1024>>>(b_l1, b_r1);

    cudaStreamWaitEvent(0, evB, 0);
    k_gat1<<<NN / 4, 256>>>(xr1, att1, bias1, b_l2, b_r2, xl2, xr2);
    k_gat2<<<(NN + 63) / 64, 256>>>(xl2, xr2, att2, bias2, out);
}